// round 4
// baseline (speedup 1.0000x reference)
#include <cuda_runtime.h>

#define NUM_BUCKETS 9311
#define D4 16   // 64 channels / 4 floats per float4

__device__ __forceinline__ unsigned long long addx2(unsigned long long a, unsigned long long b) {
    unsigned long long r;
    asm("add.rn.f32x2 %0, %1, %2;" : "=l"(r) : "l"(a), "l"(b));
    return r;
}
__device__ __forceinline__ unsigned long long mulx2(unsigned long long a, unsigned long long b) {
    unsigned long long r;
    asm("mul.rn.f32x2 %0, %1, %2;" : "=l"(r) : "l"(a), "l"(b));
    return r;
}

union F4U {
    float4 f;
    unsigned long long u[2];
};

// Reduce 8 float4s (as u64 pairs) with packed f32x2 adds, scale by inv, return.
__device__ __forceinline__ float4 reduce8(const F4U* e, unsigned long long inv2) {
    unsigned long long s0a = addx2(e[0].u[0], e[1].u[0]), s0b = addx2(e[0].u[1], e[1].u[1]);
    unsigned long long s1a = addx2(e[2].u[0], e[3].u[0]), s1b = addx2(e[2].u[1], e[3].u[1]);
    unsigned long long s2a = addx2(e[4].u[0], e[5].u[0]), s2b = addx2(e[4].u[1], e[5].u[1]);
    unsigned long long s3a = addx2(e[6].u[0], e[7].u[0]), s3b = addx2(e[6].u[1], e[7].u[1]);
    unsigned long long t0a = addx2(s0a, s1a), t0b = addx2(s0b, s1b);
    unsigned long long t1a = addx2(s2a, s3a), t1b = addx2(s2b, s3b);
    F4U r;
    r.u[0] = mulx2(addx2(t0a, t1a), inv2);
    r.u[1] = mulx2(addx2(t0b, t1b), inv2);
    return r.f;
}

__global__ void __launch_bounds__(256)
enc_kernel(const int2* __restrict__ x2,
           const float4* __restrict__ table,
           float4* __restrict__ out,
           int n_rows) {
    int warp = (blockIdx.x * blockDim.x + threadIdx.x) >> 5;
    int lane = threadIdx.x & 31;
    int half = lane >> 4;      // each half-warp handles 2 consecutive rows
    int sub  = lane & 15;      // float4 slot within the 64-channel row

    int row0 = warp * 4 + half * 2;      // rows row0 and row0+1
    int last = n_rows - 1;
    bool v0 = (row0     < n_rows);
    bool v1 = (row0 + 1 < n_rows);
    int s0 = v0 ? row0     : last;
    int s1 = v1 ? row0 + 1 : last;

    // Lanes sub 0-3: indices for row s0; lanes 4-7: indices for row s1.
    // Two (hash<<1|mask) 15-bit codes packed per int.
    int packed = 0;
    if (sub < 8) {
        int r = (sub < 4) ? s0 : s1;
        int2 v = x2[r * 4 + (sub & 3)];
        int a = max(v.x, 0);
        int b = max(v.y, 0);
        int ha = a % NUM_BUCKETS;
        int hb = b % NUM_BUCKETS;
        packed = ((ha << 1) | (a > 0 ? 1 : 0)) | ((((hb << 1) | (b > 0 ? 1 : 0))) << 16);
    }
    int base = half << 4;

    // Row 0 codes (lanes base+0..3), row 1 codes (lanes base+4..7).
    int p0 = __shfl_sync(0xffffffffu, packed, base + 0);
    int p1 = __shfl_sync(0xffffffffu, packed, base + 1);
    int p2 = __shfl_sync(0xffffffffu, packed, base + 2);
    int p3 = __shfl_sync(0xffffffffu, packed, base + 3);
    int p4 = __shfl_sync(0xffffffffu, packed, base + 4);
    int p5 = __shfl_sync(0xffffffffu, packed, base + 5);
    int p6 = __shfl_sync(0xffffffffu, packed, base + 6);
    int p7 = __shfl_sync(0xffffffffu, packed, base + 7);

    const float4* tab = table + sub;

    // 16 independent gathers, front-batched for maximum L1tex queue fill.
    // table[0] is all zeros, so masked (x<=0 -> hash irrelevant? no: x<=0 -> relu 0
    // -> hash 0) entries contribute nothing to the sum: gathers are unconditional.
    F4U e[8], f[8];
    e[0].f = __ldg(tab + ((p0 >> 1) & 0x7FFF) * D4);
    e[1].f = __ldg(tab + (p0 >> 17) * D4);
    e[2].f = __ldg(tab + ((p1 >> 1) & 0x7FFF) * D4);
    e[3].f = __ldg(tab + (p1 >> 17) * D4);
    e[4].f = __ldg(tab + ((p2 >> 1) & 0x7FFF) * D4);
    e[5].f = __ldg(tab + (p2 >> 17) * D4);
    e[6].f = __ldg(tab + ((p3 >> 1) & 0x7FFF) * D4);
    e[7].f = __ldg(tab + (p3 >> 17) * D4);
    f[0].f = __ldg(tab + ((p4 >> 1) & 0x7FFF) * D4);
    f[1].f = __ldg(tab + (p4 >> 17) * D4);
    f[2].f = __ldg(tab + ((p5 >> 1) & 0x7FFF) * D4);
    f[3].f = __ldg(tab + (p5 >> 17) * D4);
    f[4].f = __ldg(tab + ((p6 >> 1) & 0x7FFF) * D4);
    f[5].f = __ldg(tab + (p6 >> 17) * D4);
    f[6].f = __ldg(tab + ((p7 >> 1) & 0x7FFF) * D4);
    f[7].f = __ldg(tab + (p7 >> 17) * D4);

    // Valid-count per row via popc over mask bits (positions 0,16 of each code pair).
    const int M = 0x00010001;
    int cnt0 = __popc((p0 & M) | ((p1 & M) << 2) | ((p2 & M) << 4) | ((p3 & M) << 6));
    int cnt1 = __popc((p4 & M) | ((p5 & M) << 2) | ((p6 & M) << 4) | ((p7 & M) << 6));

    float inv0 = 1.0f / (float)(cnt0 > 0 ? cnt0 : 1);
    float inv1 = 1.0f / (float)(cnt1 > 0 ? cnt1 : 1);
    unsigned int i0 = __float_as_uint(inv0);
    unsigned int i1 = __float_as_uint(inv1);
    unsigned long long inv2_0 = ((unsigned long long)i0 << 32) | i0;
    unsigned long long inv2_1 = ((unsigned long long)i1 << 32) | i1;

    float4 r0 = reduce8(e, inv2_0);
    float4 r1 = reduce8(f, inv2_1);

    if (v0) out[(long long)row0 * D4 + sub] = r0;
    if (v1) out[((long long)row0 + 1) * D4 + sub] = r1;
}

extern "C" void kernel_launch(void* const* d_in, const int* in_sizes, int n_in,
                              void* d_out, int out_size) {
    const int2*   x2    = (const int2*)d_in[0];
    const float4* table = (const float4*)d_in[1];
    float4*       out   = (float4*)d_out;

    int n_rows = in_sizes[0] / 8;        // B*C = 262144
    int threads = 256;                   // 8 warps, 4 rows per warp -> 32 rows/block
    int rows_per_block = (threads / 32) * 4;
    int blocks = (n_rows + rows_per_block - 1) / rows_per_block;

    enc_kernel<<<blocks, threads>>>(x2, table, out, n_rows);
}

// round 5
// speedup vs baseline: 1.2152x; 1.2152x over previous
#include <cuda_runtime.h>
#include <cuda_fp16.h>

#define NUM_BUCKETS 9311
#define L 8          // categories per (b,c)
#define ROW_U2 16    // 64 halves per table row = 16 uint2 (8 B per lane)

// fp16 copy of the embedding table: 9311 rows x 64 ch = 1.19 MB scratch.
__device__ __half2 g_tab16[NUM_BUCKETS * 32];

__global__ void __launch_bounds__(256)
convert_kernel(const float2* __restrict__ table_f32) {
    int i = blockIdx.x * blockDim.x + threadIdx.x;       // one half2 per thread
    if (i < NUM_BUCKETS * 32) {
        float2 v = table_f32[i];
        g_tab16[i] = __floats2half2_rn(v.x, v.y);
    }
}

__global__ void __launch_bounds__(256)
enc_kernel(const int2* __restrict__ x2,
           float4* __restrict__ out,
           int n_rows) {
    int warp = (blockIdx.x * blockDim.x + threadIdx.x) >> 5;
    int lane = threadIdx.x & 31;
    int half = lane >> 4;      // which of the 2 rows this warp handles
    int sub  = lane & 15;      // uint2 slot within the 64-channel fp16 row

    int row = warp * 2 + half;
    bool valid = (row < n_rows);
    int srow = valid ? row : (n_rows - 1);   // clamp: all lanes stay active for shfl

    // Lanes sub<4 each load 2 indices; pack two (hash<<1|mask) 15-bit codes per int.
    int packed = 0;
    if (sub < 4) {
        int2 v = x2[srow * 4 + sub];
        int a = max(v.x, 0);
        int b = max(v.y, 0);
        int ha = a % NUM_BUCKETS;
        int hb = b % NUM_BUCKETS;
        packed = ((ha << 1) | (a > 0 ? 1 : 0)) | ((((hb << 1) | (b > 0 ? 1 : 0))) << 16);
    }
    int base = half << 4;

    int p0 = __shfl_sync(0xffffffffu, packed, base + 0);
    int p1 = __shfl_sync(0xffffffffu, packed, base + 1);
    int p2 = __shfl_sync(0xffffffffu, packed, base + 2);
    int p3 = __shfl_sync(0xffffffffu, packed, base + 3);

    int h0 = (p0 >> 1) & 0x7FFF, h1 = p0 >> 17;
    int h2 = (p1 >> 1) & 0x7FFF, h3 = p1 >> 17;
    int h4 = (p2 >> 1) & 0x7FFF, h5 = p2 >> 17;
    int h6 = (p3 >> 1) & 0x7FFF, h7 = p3 >> 17;

    const int M = 0x00010001;
    int cnt = __popc((p0 & M) | ((p1 & M) << 2) | ((p2 & M) << 4) | ((p3 & M) << 6));

    // Unconditional fp16 gathers (table row 0 is all zeros -> masked entries add 0).
    // 8 independent LDG.64, front-batched. Each lane: uint2 = 2 half2 = 4 channels.
    const uint2* tab = reinterpret_cast<const uint2*>(g_tab16) + sub;
    uint2 g0 = __ldg(tab + h0 * ROW_U2);
    uint2 g1 = __ldg(tab + h1 * ROW_U2);
    uint2 g2 = __ldg(tab + h2 * ROW_U2);
    uint2 g3 = __ldg(tab + h3 * ROW_U2);
    uint2 g4 = __ldg(tab + h4 * ROW_U2);
    uint2 g5 = __ldg(tab + h5 * ROW_U2);
    uint2 g6 = __ldg(tab + h6 * ROW_U2);
    uint2 g7 = __ldg(tab + h7 * ROW_U2);

    // Full HADD2 tree in fp16 (14 HADD2), then widen once.
    #define H2(v) (*reinterpret_cast<const __half2*>(&(v)))
    __half2 a01 = __hadd2(H2(g0.x), H2(g1.x));
    __half2 b01 = __hadd2(H2(g0.y), H2(g1.y));
    __half2 a23 = __hadd2(H2(g2.x), H2(g3.x));
    __half2 b23 = __hadd2(H2(g2.y), H2(g3.y));
    __half2 a45 = __hadd2(H2(g4.x), H2(g5.x));
    __half2 b45 = __hadd2(H2(g4.y), H2(g5.y));
    __half2 a67 = __hadd2(H2(g6.x), H2(g7.x));
    __half2 b67 = __hadd2(H2(g6.y), H2(g7.y));
    __half2 a03 = __hadd2(a01, a23);
    __half2 b03 = __hadd2(b01, b23);
    __half2 a47 = __hadd2(a45, a67);
    __half2 b47 = __hadd2(b45, b67);
    __half2 sa  = __hadd2(a03, a47);
    __half2 sb  = __hadd2(b03, b47);
    #undef H2

    float2 fa = __half22float2(sa);
    float2 fb = __half22float2(sb);

    float inv = 1.0f / (float)(cnt > 0 ? cnt : 1);
    float4 res = make_float4(fa.x * inv, fa.y * inv, fb.x * inv, fb.y * inv);

    if (valid) out[(long long)row * 16 + sub] = res;
}

extern "C" void kernel_launch(void* const* d_in, const int* in_sizes, int n_in,
                              void* d_out, int out_size) {
    const int2*   x2    = (const int2*)d_in[0];
    const float2* tabf  = (const float2*)d_in[1];
    float4*       out   = (float4*)d_out;

    // 1) table f32 -> fp16 scratch (idempotent, graph-capturable)
    int n_h2 = NUM_BUCKETS * 32;
    convert_kernel<<<(n_h2 + 255) / 256, 256>>>(tabf);

    // 2) main gather kernel (R3-proven shape: 2 rows/warp, 256 threads)
    int n_rows = in_sizes[0] / L;        // B*C = 262144
    int threads = 256;
    int rows_per_block = (threads / 32) * 2;
    int blocks = (n_rows + rows_per_block - 1) / rows_per_block;

    enc_kernel<<<blocks, threads>>>(x2, out, n_rows);
}